// round 14
// baseline (speedup 1.0000x reference)
#include <cuda_runtime.h>
#include <cuda_fp16.h>
#include <cstdint>
#include <math.h>

#define BB 2
#define TT 2048
#define CC 1024
#define HH 16
#define HD 64
#define NBH 32
#define C3 3072

// ---------------- device scratch (never passed as kernel args) ----------------
__device__ __half g_xh[BB*TT*CC];
__device__ __half g_xl[BB*TT*CC];
__device__ __half g_wqkvTh[C3*CC];      // [n][k] hi
__device__ __half g_woutTh[CC*CC];      // [n][k] hi
__device__ __half g_qh[NBH*TT*HD];      // [bh][t][d]
__device__ __half g_ql[NBH*TT*HD];
__device__ __half g_kh[NBH*TT*HD];
__device__ __half g_vth[NBH*HD*TT];     // [bh][d][t]
__device__ __half g_oh[NBH*TT*HD];
__device__ __half g_ol[NBH*TT*HD];
__device__ float g_rinv[NBH*TT];
__device__ float g_cos[TT*32];
__device__ float g_sin[TT*32];

#define STR32 40
#define STR64 72

// ---------------- helpers ----------------
__device__ __forceinline__ uint32_t s2u(const void* p) {
    uint32_t a;
    asm("{ .reg .u64 t; cvta.to.shared.u64 t, %1; cvt.u32.u64 %0, t; }" : "=r"(a) : "l"(p));
    return a;
}
#define CPA16(sa, gp) asm volatile("cp.async.cg.shared.global [%0], [%1], 16;" :: "r"(sa), "l"(gp) : "memory")
#define CPA_COMMIT()  asm volatile("cp.async.commit_group;" ::: "memory")
#define CPA_WAIT2()   asm volatile("cp.async.wait_group 2;" ::: "memory")
#define CPA_WAIT1()   asm volatile("cp.async.wait_group 1;" ::: "memory")
#define CPA_WAIT0()   asm volatile("cp.async.wait_group 0;" ::: "memory")

__device__ __forceinline__ void mma16816(float* d, const uint32_t* a, uint32_t b0, uint32_t b1) {
    asm volatile("mma.sync.aligned.m16n8k16.row.col.f32.f16.f16.f32 "
                 "{%0,%1,%2,%3}, {%4,%5,%6,%7}, {%8,%9}, {%0,%1,%2,%3};"
                 : "+f"(d[0]), "+f"(d[1]), "+f"(d[2]), "+f"(d[3])
                 : "r"(a[0]), "r"(a[1]), "r"(a[2]), "r"(a[3]), "r"(b0), "r"(b1));
}
__device__ __forceinline__ void ldm4(uint32_t* r, uint32_t a) {
    asm volatile("ldmatrix.sync.aligned.m8n8.x4.shared.b16 {%0,%1,%2,%3}, [%4];"
                 : "=r"(r[0]), "=r"(r[1]), "=r"(r[2]), "=r"(r[3]) : "r"(a));
}
__device__ __forceinline__ void ldm2(uint32_t* r, uint32_t a) {
    asm volatile("ldmatrix.sync.aligned.m8n8.x2.shared.b16 {%0,%1}, [%2];"
                 : "=r"(r[0]), "=r"(r[1]) : "r"(a));
}
__device__ __forceinline__ __half2 h2hi(float a, float b) {
    return __halves2half2(__float2half_rn(a), __float2half_rn(b));
}
__device__ __forceinline__ __half2 h2lo(float a, float b, __half2 h) {
    return __halves2half2(__float2half_rn(a - __low2float(h)),
                          __float2half_rn(b - __high2float(h)));
}
// hi-only store of a float4 (P operand in k_pv)
__device__ __forceinline__ void st_h(__half* hi, int idx, float4 v) {
    __half2 H0 = h2hi(v.x, v.y), H1 = h2hi(v.z, v.w);
    uint2 HU;
    HU.x = *reinterpret_cast<uint32_t*>(&H0); HU.y = *reinterpret_cast<uint32_t*>(&H1);
    *reinterpret_cast<uint2*>(hi + idx) = HU;
}

// ---------------- RoPE table ----------------
__global__ void k_rope_tab() {
    int idx = blockIdx.x * 256 + threadIdx.x;
    if (idx >= TT * 32) return;
    int t = idx / 32, j = idx % 32;
    int mi = (2 * j) % 32;
    float inv32 = (float)pow(10000.0, -(double)mi / 32.0);
    float th32 = (float)t * inv32;
    g_cos[idx] = (float)cos((double)th32);
    g_sin[idx] = (float)sin((double)th32);
}

// ---------------- split x into fp16 hi/lo ----------------
__global__ void k_half_x(const float* __restrict__ x) {
    int idx = (blockIdx.x * 256 + threadIdx.x) * 4;
    float4 v = *(const float4*)(x + idx);
    __half2 H0 = h2hi(v.x, v.y), H1 = h2hi(v.z, v.w);
    __half2 L0 = h2lo(v.x, v.y, H0), L1 = h2lo(v.z, v.w, H1);
    uint2 HU, LU;
    HU.x = *reinterpret_cast<uint32_t*>(&H0); HU.y = *reinterpret_cast<uint32_t*>(&H1);
    LU.x = *reinterpret_cast<uint32_t*>(&L0); LU.y = *reinterpret_cast<uint32_t*>(&L1);
    *reinterpret_cast<uint2*>(g_xh + idx) = HU;
    *reinterpret_cast<uint2*>(g_xl + idx) = LU;
}

// ---------------- transpose + fp16 convert: src[K][N] -> dst[N][K] ----------------
__global__ void k_transpose(const float* __restrict__ src, int which, int K, int N) {
    __shared__ float tb[32][33];
    __half* dst = which ? g_woutTh : g_wqkvTh;
    int n0 = blockIdx.x * 32, k0 = blockIdx.y * 32;
    for (int i = threadIdx.y; i < 32; i += 8)
        tb[i][threadIdx.x] = src[(size_t)(k0 + i) * N + n0 + threadIdx.x];
    __syncthreads();
    for (int i = threadIdx.y; i < 32; i += 8)
        dst[(size_t)(n0 + i) * K + k0 + threadIdx.x] = __float2half_rn(tb[threadIdx.x][i]);
}

// ---------------- K1: QKV GEMM (HMMA 2-pass, cp.async 3-stage) ----------------
#define QKV_STAGE 15360    // halves per stage: Ah 5120 + Al 5120 + Bh 5120
__global__ __launch_bounds__(256, 2) void k_qkv() {
    extern __shared__ __half sm[];
    const int tid = threadIdx.x, lane = tid & 31, wid = tid >> 5;
    const int wm = wid & 1, wn = wid >> 1, g = lane >> 2, tg = lane & 3;
    const int bn = blockIdx.x * 128, bm = blockIdx.y * 128;
    const int l15 = lane & 15;
    const uint32_t su = s2u(sm);
    const int fr0 = tid >> 2, fc0 = tid & 3;
    const int fr1 = fr0 + 64;

    float acc[4][4][4] = {};
    const uint32_t aOffH = (uint32_t)(((wm*64 + l15) * STR32 + (lane >> 4) * 8) << 1);
    const uint32_t aOffL = aOffH + 5120 * 2;
    const uint32_t bOff  = (uint32_t)((10240 + (wn*32 + (l15 & 7)) * STR32 + (l15 >> 3) * 8) << 1);

    auto fill = [&](int c, int s) {
        uint32_t sb = su + (uint32_t)((s * QKV_STAGE) << 1);
        size_t gA0 = (size_t)(bm+fr0)*CC + c*32 + fc0*8;
        size_t gA1 = (size_t)(bm+fr1)*CC + c*32 + fc0*8;
        CPA16(sb + (uint32_t)((fr0*STR32 + fc0*8) << 1),          g_xh + gA0);
        CPA16(sb + (uint32_t)((fr1*STR32 + fc0*8) << 1),          g_xh + gA1);
        CPA16(sb + (uint32_t)((5120 + fr0*STR32 + fc0*8) << 1),   g_xl + gA0);
        CPA16(sb + (uint32_t)((5120 + fr1*STR32 + fc0*8) << 1),   g_xl + gA1);
        CPA16(sb + (uint32_t)((10240 + fr0*STR32 + fc0*8) << 1),  g_wqkvTh + (size_t)(bn+fr0)*CC + c*32 + fc0*8);
        CPA16(sb + (uint32_t)((10240 + fr1*STR32 + fc0*8) << 1),  g_wqkvTh + (size_t)(bn+fr1)*CC + c*32 + fc0*8);
    };

    fill(0, 0); CPA_COMMIT();
    fill(1, 1); CPA_COMMIT();
    for (int c = 0; c < 32; c++) {
        int s = c % 3;
        if (c < 30)      { fill(c+2, (c+2) % 3); CPA_COMMIT(); CPA_WAIT2(); }
        else if (c == 30) CPA_WAIT1();
        else              CPA_WAIT0();
        __syncthreads();
        uint32_t stb = su + (uint32_t)((s * QKV_STAGE) << 1);
        #pragma unroll
        for (int ks = 0; ks < 2; ks++) {
            uint32_t ah[4][4], al[4][4], bf[4][2];
            #pragma unroll
            for (int mf = 0; mf < 4; mf++) {
                uint32_t off = (uint32_t)((mf*16*STR32 + ks*16) << 1);
                ldm4(ah[mf], stb + aOffH + off);
                ldm4(al[mf], stb + aOffL + off);
            }
            #pragma unroll
            for (int nf = 0; nf < 4; nf++)
                ldm2(bf[nf], stb + bOff + (uint32_t)((nf*8*STR32 + ks*16) << 1));
            #pragma unroll
            for (int nf = 0; nf < 4; nf++)
                #pragma unroll
                for (int mf = 0; mf < 4; mf++) {
                    mma16816(acc[mf][nf], ah[mf], bf[nf][0], bf[nf][1]);
                    mma16816(acc[mf][nf], al[mf], bf[nf][0], bf[nf][1]);
                }
        }
        __syncthreads();
    }
    #pragma unroll
    for (int mf = 0; mf < 4; mf++) {
        #pragma unroll
        for (int half = 0; half < 2; half++) {
            int m = bm + wm*64 + mf*16 + g + half*8;
            int b = m >> 11, t = m & 2047;
            #pragma unroll
            for (int nf = 0; nf < 4; nf++) {
                int n = bn + wn*32 + nf*8 + 2*tg;
                float v0 = acc[mf][nf][half*2 + 0], v1 = acc[mf][nf][half*2 + 1];
                int sect = n >> 10, rem = n & 1023, hh = rem >> 6, d = rem & 63;
                if (sect == 2) {
                    size_t base = ((size_t)(b*HH + hh) * HD + d) * TT + t;
                    g_vth[base] = __float2half_rn(v0);
                    g_vth[base + TT] = __float2half_rn(v1);
                } else {
                    int j2 = d >> 1;
                    float cs = g_cos[t*32 + j2], sn = g_sin[t*32 + j2];
                    float r0 = v0*cs - v1*sn, r1 = v1*cs + v0*sn;
                    size_t idx = ((size_t)(b*HH + hh)*TT + t)*HD + d;
                    __half2 hi = h2hi(r0, r1);
                    if (sect == 0) {
                        *(__half2*)(g_qh + idx) = hi;
                        *(__half2*)(g_ql + idx) = h2lo(r0, r1, hi);
                    } else {
                        *(__half2*)(g_kh + idx) = hi;
                    }
                }
            }
        }
    }
}

// ---------------- K2: attn <- exp(QK^T/8 - alibi); g_rinv <- 1/rowsum -------------
// smem: Qh 9216 | Ql 9216 | Kh stages 3*9216 | srd 512 floats
__global__ __launch_bounds__(256, 2) void k_scores(float* __restrict__ attn) {
    extern __shared__ __half sm[];
    __half* Qh = sm;
    __half* Ql = sm + 9216;
    float* srd_s = (float*)(sm + 46080);   // [4][128]
    const int tid = threadIdx.x, lane = tid & 31, wid = tid >> 5;
    const int wm = wid & 1, wn = wid >> 1, g = lane >> 2, tg = lane & 3;
    const int bh = blockIdx.y, h = bh & 15, q0 = blockIdx.x * 128;
    const int l15 = lane & 15;
    const uint32_t su = s2u(sm);
    const __half* qhb = g_qh + (size_t)bh * TT * HD;
    const __half* qlb = g_ql + (size_t)bh * TT * HD;
    const __half* khb = g_kh + (size_t)bh * TT * HD;

    #pragma unroll
    for (int i = 0; i < 4; i++) {
        int f = tid + i*256, row = f >> 3, c8 = f & 7;
        size_t go = (size_t)(q0+row)*HD + c8*8;
        *(uint4*)(Qh + row*STR64 + c8*8) = *(const uint4*)(qhb + go);
        *(uint4*)(Ql + row*STR64 + c8*8) = *(const uint4*)(qlb + go);
    }
    const uint32_t aBaseH = su + (uint32_t)(((wm*64 + l15) * STR64 + (lane >> 4) * 8) << 1);
    const uint32_t aBaseL = aBaseH + 9216 * 2;
    const uint32_t bOff   = (uint32_t)(((wn*32 + (l15 & 7)) * STR64 + (l15 >> 3) * 8) << 1);
    const float slope = exp2f(-0.5f * (float)(h + 1));
    float rs[8];
    #pragma unroll
    for (int i = 0; i < 8; i++) rs[i] = 0.f;

    auto fillK = [&](int nt, int s) {
        uint32_t sb = su + (uint32_t)((18432 + s*9216) << 1);
        #pragma unroll
        for (int i = 0; i < 4; i++) {
            int f = tid + i*256, row = f >> 3, c8 = f & 7;
            CPA16(sb + (uint32_t)((row*STR64 + c8*8) << 1),
                  khb + (size_t)(nt*128+row)*HD + c8*8);
        }
    };

    fillK(0, 0); CPA_COMMIT();
    fillK(1, 1); CPA_COMMIT();
    for (int nt = 0; nt < 16; nt++) {
        int s = nt % 3;
        if (nt < 14)      { fillK(nt+2, (nt+2) % 3); CPA_COMMIT(); CPA_WAIT2(); }
        else if (nt == 14) CPA_WAIT1();
        else               CPA_WAIT0();
        __syncthreads();
        uint32_t bBase = su + (uint32_t)((18432 + s*9216) << 1) + bOff;
        float acc[4][4][4] = {};
        #pragma unroll
        for (int ks = 0; ks < 4; ks++) {
            uint32_t ah[4][4], al[4][4], bf[4][2];
            #pragma unroll
            for (int mf = 0; mf < 4; mf++) {
                uint32_t off = (uint32_t)((mf*16*STR64 + ks*16) << 1);
                ldm4(ah[mf], aBaseH + off);
                ldm4(al[mf], aBaseL + off);
            }
            #pragma unroll
            for (int nf = 0; nf < 4; nf++)
                ldm2(bf[nf], bBase + (uint32_t)((nf*8*STR64 + ks*16) << 1));
            #pragma unroll
            for (int nf = 0; nf < 4; nf++)
                #pragma unroll
                for (int mf = 0; mf < 4; mf++) {
                    mma16816(acc[mf][nf], ah[mf], bf[nf][0], bf[nf][1]);
                    mma16816(acc[mf][nf], al[mf], bf[nf][0], bf[nf][1]);
                }
        }
        #pragma unroll
        for (int mf = 0; mf < 4; mf++) {
            #pragma unroll
            for (int half = 0; half < 2; half++) {
                int r = wm*64 + mf*16 + g + half*8;
                int q = q0 + r;
                float ssum = 0.f;
                #pragma unroll
                for (int nf = 0; nf < 4; nf++) {
                    int col = nt*128 + wn*32 + nf*8 + 2*tg;
                    float e0 = __expf(acc[mf][nf][half*2+0] * 0.125f - slope * fabsf((float)(q - col)));
                    float e1 = __expf(acc[mf][nf][half*2+1] * 0.125f - slope * fabsf((float)(q - col - 1)));
                    *(float2*)(attn + ((size_t)bh*TT + q)*TT + col) = make_float2(e0, e1);
                    ssum += e0 + e1;
                }
                rs[mf*2 + half] += ssum;
            }
        }
        __syncthreads();
    }
    #pragma unroll
    for (int i = 0; i < 8; i++) {
        rs[i] += __shfl_xor_sync(0xffffffffu, rs[i], 1);
        rs[i] += __shfl_xor_sync(0xffffffffu, rs[i], 2);
    }
    if (tg == 0) {
        #pragma unroll
        for (int mf = 0; mf < 4; mf++)
            #pragma unroll
            for (int half = 0; half < 2; half++) {
                int r = wm*64 + mf*16 + g + half*8;
                srd_s[wn*128 + r] = rs[mf*2 + half];
            }
    }
    __syncthreads();
    if (tid < 128) {
        float s = srd_s[tid] + srd_s[128 + tid] + srd_s[256 + tid] + srd_s[384 + tid];
        g_rinv[(size_t)bh*TT + q0 + tid] = 1.0f / s;
    }
}

// ---------------- K3: P = E * rinv (final attn) + O = P @ V (P hi-only) ------------
__global__ __launch_bounds__(256, 2) void k_pv(float* __restrict__ attn) {
    extern __shared__ __half sm[];
    __half* Ph = sm;              // 256*40 = 10240
    __half* Vh = sm + 10240;      // 64*40 = 2560
    float* sri = (float*)(sm + 12800);   // 256
    const int tid = threadIdx.x, lane = tid & 31, wid = tid >> 5;
    const int wm = wid & 3, wn = wid >> 2, g = lane >> 2, tg = lane & 3;
    const int bh = blockIdx.y, q0 = blockIdx.x * 256;
    const int l15 = lane & 15;
    sri[tid] = g_rinv[(size_t)bh*TT + q0 + tid];
    __syncthreads();
    float acc[4][4][4] = {};
    const uint32_t aBase = s2u(Ph) + (((wm*64 + l15) * STR32 + (lane >> 4) * 8) << 1);
    const uint32_t bBase = s2u(Vh) + (((wn*32 + (l15 & 7)) * STR32 + (l15 >> 3) * 8) << 1);
    const __half* vtb = g_vth + (size_t)bh * HD * TT;

    for (int c = 0; c < 64; c++) {
        #pragma unroll
        for (int i = 0; i < 8; i++) {
            int f = tid + i*256, row = f >> 3, c4 = f & 7;
            size_t off = ((size_t)bh*TT + q0 + row)*TT + c*32 + c4*4;
            float4 v = *(const float4*)(attn + off);
            float iv = sri[row];
            float4 p;
            p.x = v.x * iv;
            p.y = v.y * iv;
            p.z = v.z * iv;
            p.w = v.w * iv;
            *(float4*)(attn + off) = p;               // final attn output (fp32, exact)
            st_h(Ph, row*STR32 + c4*4, p);
        }
        {
            int row = tid >> 2, c8 = tid & 3;
            *(uint4*)(Vh + row*STR32 + c8*8) = *(const uint4*)(vtb + (size_t)row*TT + c*32 + c8*8);
        }
        __syncthreads();
        #pragma unroll
        for (int ks = 0; ks < 2; ks++) {
            uint32_t ah[4][4], bf[4][2];
            #pragma unroll
            for (int mf = 0; mf < 4; mf++)
                ldm4(ah[mf], aBase + (uint32_t)((mf*16*STR32 + ks*16) << 1));
            #pragma unroll
            for (int nf = 0; nf < 4; nf++)
                ldm2(bf[nf], bBase + (uint32_t)((nf*8*STR32 + ks*16) << 1));
            #pragma unroll
            for (int nf = 0; nf < 4; nf++)
                #pragma unroll
                for (int mf = 0; mf < 4; mf++)
                    mma16816(acc[mf][nf], ah[mf], bf[nf][0], bf[nf][1]);
        }
        __syncthreads();
    }
    #pragma unroll
    for (int mf = 0; mf < 4; mf++) {
        int r = q0 + wm*64 + mf*16 + g;
        #pragma unroll
        for (int nf = 0; nf < 4; nf++) {
            int ccol = wn*32 + nf*8 + 2*tg;
            size_t i0 = ((size_t)bh*TT + r)*HD + ccol;
            size_t i1 = ((size_t)bh*TT + r + 8)*HD + ccol;
            __half2 h0 = h2hi(acc[mf][nf][0], acc[mf][nf][1]);
            __half2 h1 = h2hi(acc[mf][nf][2], acc[mf][nf][3]);
            *(__half2*)(g_oh + i0) = h0;
            *(__half2*)(g_ol + i0) = h2lo(acc[mf][nf][0], acc[mf][nf][1], h0);
            *(__half2*)(g_oh + i1) = h1;
            *(__half2*)(g_ol + i1) = h2lo(acc[mf][nf][2], acc[mf][nf][3], h1);
        }
    }
}

// ---------------- K4: out = O @ W_out + b (cp.async 3-stage) ----------------
__global__ __launch_bounds__(256, 2) void k_outproj(const float* __restrict__ bout,
                                                    float* __restrict__ out) {
    extern __shared__ __half sm[];
    const int tid = threadIdx.x, lane = tid & 31, wid = tid >> 5;
    const int wm = wid & 1, wn = wid >> 1, g = lane >> 2, tg = lane & 3;
    const int bn = blockIdx.x * 128, bm = blockIdx.y * 128;
    const int l15 = lane & 15;
    const uint32_t su = s2u(sm);
    const int fr0 = tid >> 2, fc0 = tid & 3;
    const int fr1 = fr0 + 64;

    float acc[4][4][4] = {};
    const uint32_t aOffH = (uint32_t)(((wm*64 + l15) * STR32 + (lane >> 4) * 8) << 1);
    const uint32_t aOffL = aOffH + 5120 * 2;
    const uint32_t bOff  = (uint32_t)((10240 + (wn*32 + (l15 & 7)) * STR32 + (l15 >> 3) * 8) << 1);

    auto fill = [&](int c, int s) {
        uint32_t sb = su + (uint32_t)((s * QKV_STAGE) << 1);
        #pragma unroll
        for (int half = 0; half < 2; half++) {
            int row = half ? fr1 : fr0;
            int m = bm + row, b = m >> 11, t = m & 2047;
            int kk = c*32 + fc0*8, hh = kk >> 6, dd = kk & 63;
            size_t go = ((size_t)(b*HH + hh)*TT + t)*HD + dd;
            CPA16(sb + (uint32_t)((row*STR32 + fc0*8) << 1),         g_oh + go);
            CPA16(sb + (uint32_t)((5120 + row*STR32 + fc0*8) << 1),  g_ol + go);
            CPA16(sb + (uint32_t)((10240 + row*STR32 + fc0*8) << 1), g_woutTh + (size_t)(bn+row)*CC + c*32 + fc0*8);
        }
    };

    fill(0, 0); CPA_COMMIT();
    fill(1, 1); CPA_COMMIT();
    for (int c = 0; c < 32; c++) {
        int s = c % 3;
        if (c < 30)      { fill(c+2, (c+2) % 3); CPA_COMMIT(); CPA_WAIT2(); }
        else if (c == 30) CPA_WAIT1();
        else              CPA_WAIT0();
        __syncthreads();
        uint32_t stb = su + (uint32_t)((s * QKV_STAGE) << 1);
        #pragma unroll
        for (int ks = 0; ks < 2; ks++) {
            uint32_t ah[4][4], al[4][4], bf[4][2];
            #pragma unroll
            for (int mf = 0; mf < 4; mf++) {
                uint32_t off = (uint32_t)((mf*16*STR32 + ks*16) << 1);
                ldm4(ah[mf], stb + aOffH + off);
                ldm4(al[mf], stb + aOffL + off);
            }
            #pragma unroll
            for (int nf = 0; nf < 4; nf++)
                ldm2(bf[nf], stb + bOff + (uint32_t)((nf*8*STR32 + ks*16) << 1));
            #pragma unroll
            for (int nf = 0; nf < 4; nf++)
                #pragma unroll
                for (int mf = 0; mf < 4; mf++) {
                    mma16816(acc[mf][nf], ah[mf], bf[nf][0], bf[nf][1]);
                    mma16816(acc[mf][nf], al[mf], bf[nf][0], bf[nf][1]);
                }
        }
        __syncthreads();
    }
    #pragma unroll
    for (int mf = 0; mf < 4; mf++) {
        #pragma unroll
        for (int half = 0; half < 2; half++) {
            int m = bm + wm*64 + mf*16 + g + half*8;
            #pragma unroll
            for (int nf = 0; nf < 4; nf++) {
                int n = bn + wn*32 + nf*8 + 2*tg;
                float2 o = make_float2(acc[mf][nf][half*2+0] + bout[n],
                                       acc[mf][nf][half*2+1] + bout[n+1]);
                *(float2*)(out + (size_t)m*CC + n) = o;
            }
        }
    }
}

// ---------------- launch ----------------
extern "C" void kernel_launch(void* const* d_in, const int* in_sizes, int n_in,
                              void* d_out, int out_size) {
    const float* x    = (const float*)d_in[0];
    const float* Wqkv = (const float*)d_in[1];
    const float* Wout = (const float*)d_in[2];
    const float* bout = (const float*)d_in[3];
    float* out  = (float*)d_out;
    float* attn = out + (size_t)BB * TT * CC;

    cudaFuncSetAttribute(k_qkv,     cudaFuncAttributeMaxDynamicSharedMemorySize, 92160);
    cudaFuncSetAttribute(k_scores,  cudaFuncAttributeMaxDynamicSharedMemorySize, 94208);
    cudaFuncSetAttribute(k_pv,      cudaFuncAttributeMaxDynamicSharedMemorySize, 26624);
    cudaFuncSetAttribute(k_outproj, cudaFuncAttributeMaxDynamicSharedMemorySize, 92160);

    k_rope_tab<<<256, 256>>>();
    k_half_x<<<(BB*TT*CC)/1024, 256>>>(x);
    k_transpose<<<dim3(C3 / 32, CC / 32), dim3(32, 8)>>>(Wqkv, 0, CC, C3);
    k_transpose<<<dim3(CC / 32, CC / 32), dim3(32, 8)>>>(Wout, 1, CC, CC);
    k_qkv    <<<dim3(C3 / 128, (BB * TT) / 128), 256, 92160>>>();
    k_scores <<<dim3(TT / 128, NBH), 256, 94208>>>(attn);
    k_pv     <<<dim3(TT / 256, NBH), 256, 26624>>>(attn);
    k_outproj<<<dim3(CC / 128, (BB * TT) / 128), 256, 92160>>>(bout, out);
}